// round 1
// baseline (speedup 1.0000x reference)
#include <cuda_runtime.h>
#include <cuda_bf16.h>
#include <cstdint>

// Banded stereo cost volume, 3 scales, fused in one kernel.
// cost[j,h,x] = sum_c L[c,h,x] * R[c,h,x-j], zero when x<j.
//
// Strategy: one CTA per image row. Stage L row (C*W) and a left-zero-padded
// R row (C*(D+W)) in shared memory, then register-tile TJ=8 disparities x
// TX=4 columns per thread. The D-float zero pad makes the x<j band exactly
// zero without branches. All loads are LDS.128 with 16B lane stride
// (conflict-free); FMA pipe and SMEM crossbar saturate together.

#define THREADS 256

template <int C, int H, int W, int D>
__device__ __forceinline__ void cost_volume_row(const float* __restrict__ L,
                                                const float* __restrict__ R,
                                                float* __restrict__ out,
                                                int h, float* smem)
{
    constexpr int RW = D + W;           // padded R row width
    float* sL = smem;                   // [C][W]
    float* sR = smem + C * W;           // [C][RW], first D floats per channel = 0

    const int tid = threadIdx.x;

    // Zero the pad region (small: C*D elements)
    for (int i = tid; i < C * D; i += THREADS) {
        int c = i / D;
        int k = i - c * D;
        sR[c * RW + k] = 0.0f;
    }

    // Stage L and R rows (vectorized float4). Channel stride in gmem = H*W.
    constexpr int WV = W / 4;           // power of two
    const float4* Lg = reinterpret_cast<const float4*>(L + (size_t)h * W);
    const float4* Rg = reinterpret_cast<const float4*>(R + (size_t)h * W);
    constexpr int CH_STRIDE_V = H * W / 4;
    for (int i = tid; i < C * WV; i += THREADS) {
        int c  = i / WV;                // shift (WV pow2)
        int xv = i - c * WV;
        float4 lv = Lg[(size_t)c * CH_STRIDE_V + xv];
        float4 rv = Rg[(size_t)c * CH_STRIDE_V + xv];
        reinterpret_cast<float4*>(sL + c * W)[xv] = lv;
        reinterpret_cast<float4*>(sR + c * RW + D)[xv] = rv;
    }
    __syncthreads();

    // Tile grid: TJ=8 disparities x TX=4 columns per tile.
    constexpr int NXT = W / 4;          // x tiles per row (pow2)
    constexpr int NT  = (D / 8) * NXT;  // total tiles

    for (int t = tid; t < NT; t += THREADS) {
        int jt = t / NXT;               // shift (NXT pow2)
        int xt = t - jt * NXT;
        int j0 = jt * 8;
        int x0 = xt * 4;

        float acc[8][4];
#pragma unroll
        for (int jj = 0; jj < 8; jj++)
#pragma unroll
            for (int xi = 0; xi < 4; xi++)
                acc[jj][xi] = 0.0f;

        // sR index for logical R[x-j] is D + x - j.
        // Load window base: D + x0 - j0 - 8 (16B aligned, always >= 0).
        const int rbase = D + x0 - j0 - 8;

#pragma unroll 4
        for (int c = 0; c < C; c++) {
            const float* sLc = sL + c * W + x0;
            const float* sRc = sR + c * RW + rbase;

            float4 l4 = *reinterpret_cast<const float4*>(sLc);
            float lv[4] = {l4.x, l4.y, l4.z, l4.w};

            float4 r0 = *reinterpret_cast<const float4*>(sRc);
            float4 r1 = *reinterpret_cast<const float4*>(sRc + 4);
            float4 r2 = *reinterpret_cast<const float4*>(sRc + 8);
            float rv[12] = {r0.x, r0.y, r0.z, r0.w,
                            r1.x, r1.y, r1.z, r1.w,
                            r2.x, r2.y, r2.z, r2.w};

            // k = 8 + xi - jj  in [1, 11]
#pragma unroll
            for (int jj = 0; jj < 8; jj++)
#pragma unroll
                for (int xi = 0; xi < 4; xi++)
                    acc[jj][xi] = fmaf(lv[xi], rv[8 + xi - jj], acc[jj][xi]);
        }

#pragma unroll
        for (int jj = 0; jj < 8; jj++) {
            float4 o = make_float4(acc[jj][0], acc[jj][1], acc[jj][2], acc[jj][3]);
            *reinterpret_cast<float4*>(out + (size_t)(j0 + jj) * H * W +
                                       (size_t)h * W + x0) = o;
        }
    }
}

// Output layout: cv0 (1,192,256,512) | cv1 (1,96,128,256) | cv2 (1,48,64,128)
static constexpr size_t OUT0_ELEMS = (size_t)192 * 256 * 512;  // 25165824
static constexpr size_t OUT1_ELEMS = (size_t)96 * 128 * 256;   //  3145728

__global__ void __launch_bounds__(THREADS, 1)
cost_volume_fused_kernel(const float* __restrict__ L0, const float* __restrict__ R0,
                         const float* __restrict__ L1, const float* __restrict__ R1,
                         const float* __restrict__ L2, const float* __restrict__ R2,
                         float* __restrict__ out)
{
    extern __shared__ float smem[];
    int b = blockIdx.x;
    if (b < 256) {
        cost_volume_row<32, 256, 512, 192>(L0, R0, out, b, smem);
    } else if (b < 256 + 128) {
        cost_volume_row<32, 128, 256, 96>(L1, R1, out + OUT0_ELEMS, b - 256, smem);
    } else {
        cost_volume_row<32, 64, 128, 48>(L2, R2, out + OUT0_ELEMS + OUT1_ELEMS,
                                         b - 256 - 128, smem);
    }
}

extern "C" void kernel_launch(void* const* d_in, const int* in_sizes, int n_in,
                              void* d_out, int out_size)
{
    const float* L0 = (const float*)d_in[0];
    const float* R0 = (const float*)d_in[1];
    const float* L1 = (const float*)d_in[2];
    const float* R1 = (const float*)d_in[3];
    const float* L2 = (const float*)d_in[4];
    const float* R2 = (const float*)d_in[5];
    float* out = (float*)d_out;

    // Worst-case smem: scale 0 -> 32*(512 + 192+512)*4 = 155648 bytes
    constexpr int SMEM_BYTES = 32 * (512 + 192 + 512) * 4;
    static bool attr_set = false;
    if (!attr_set) {
        cudaFuncSetAttribute(cost_volume_fused_kernel,
                             cudaFuncAttributeMaxDynamicSharedMemorySize, SMEM_BYTES);
        attr_set = true;
    }

    // 256 + 128 + 64 = 448 blocks; heavy scale-0 rows scheduled first.
    cost_volume_fused_kernel<<<448, THREADS, SMEM_BYTES>>>(L0, R0, L1, R1, L2, R2, out);
}

// round 2
// speedup vs baseline: 1.9233x; 1.9233x over previous
#include <cuda_runtime.h>
#include <cuda_bf16.h>
#include <cstdint>

// Banded stereo cost volume, 3 scales fused.
// cost[j,h,x] = sum_c L[c,h,x] * R[c,h,x-j], zero when x<j.
//
// One CTA per image row. Stage L row (C*W) and left-zero-padded R row
// (C*(D+W)) in SMEM; register-tile TJ=16 disparities x TX=4 columns per
// thread. TX=4 keeps a 16B lane stride so every LDS.128 is conflict-free.
// Tiles entirely inside the x<j zero band skip the channel loop.

#define THREADS 512

template <int C, int H, int W, int D>
__device__ __forceinline__ void cost_volume_row(const float* __restrict__ L,
                                                const float* __restrict__ R,
                                                float* __restrict__ out,
                                                int h, float* smem)
{
    constexpr int RW = D + W;           // padded R row width
    float* sL = smem;                   // [C][W]
    float* sR = smem + C * W;           // [C][RW], first D floats/channel = 0

    const int tid = threadIdx.x;

    // Zero the pad region (C*D elements)
    for (int i = tid; i < C * D; i += THREADS) {
        int c = i / D;
        int k = i - c * D;
        sR[c * RW + k] = 0.0f;
    }

    // Stage L and R rows (float4 vectorized). Channel stride in gmem = H*W.
    constexpr int WV = W / 4;
    const float4* Lg = reinterpret_cast<const float4*>(L + (size_t)h * W);
    const float4* Rg = reinterpret_cast<const float4*>(R + (size_t)h * W);
    constexpr int CH_STRIDE_V = H * W / 4;
    for (int i = tid; i < C * WV; i += THREADS) {
        int c  = i / WV;
        int xv = i - c * WV;
        float4 lv = Lg[(size_t)c * CH_STRIDE_V + xv];
        float4 rv = Rg[(size_t)c * CH_STRIDE_V + xv];
        reinterpret_cast<float4*>(sL + c * W)[xv] = lv;
        reinterpret_cast<float4*>(sR + c * RW + D)[xv] = rv;
    }
    __syncthreads();

    // Tile grid: TJ=16 disparities x TX=4 columns per tile.
    constexpr int NXT = W / 4;              // x tiles (pow2, >= 32)
    constexpr int NT  = (D / 16) * NXT;     // total tiles

    for (int t = tid; t < NT; t += THREADS) {
        int jt = t / NXT;                   // shift (NXT pow2)
        int xt = t - jt * NXT;
        int j0 = jt * 16;
        int x0 = xt * 4;

        float* op = out + (size_t)j0 * H * W + (size_t)h * W + x0;

        // Entire tile inside the x<j zero band: write zeros, skip compute.
        if (x0 + 3 < j0) {
            float4 z = make_float4(0.f, 0.f, 0.f, 0.f);
#pragma unroll
            for (int jj = 0; jj < 16; jj++)
                *reinterpret_cast<float4*>(op + (size_t)jj * H * W) = z;
            continue;
        }

        float acc[16][4];
#pragma unroll
        for (int jj = 0; jj < 16; jj++)
#pragma unroll
            for (int xi = 0; xi < 4; xi++)
                acc[jj][xi] = 0.0f;

        // sR index of logical R[x-j] is D + x - j.
        // Window base D + x0 - j0 - 16: >= 0, multiple of 4 (16B aligned).
        const int rbase = D + x0 - j0 - 16;

#pragma unroll 4
        for (int c = 0; c < C; c++) {
            const float* sLc = sL + c * W + x0;
            const float* sRc = sR + c * RW + rbase;

            float4 l4 = *reinterpret_cast<const float4*>(sLc);
            float lv[4] = {l4.x, l4.y, l4.z, l4.w};

            float rv[20];
#pragma unroll
            for (int q = 0; q < 5; q++) {
                float4 r4 = *reinterpret_cast<const float4*>(sRc + 4 * q);
                rv[4 * q + 0] = r4.x; rv[4 * q + 1] = r4.y;
                rv[4 * q + 2] = r4.z; rv[4 * q + 3] = r4.w;
            }

            // k = 16 + xi - jj in [1, 19]
#pragma unroll
            for (int jj = 0; jj < 16; jj++)
#pragma unroll
                for (int xi = 0; xi < 4; xi++)
                    acc[jj][xi] = fmaf(lv[xi], rv[16 + xi - jj], acc[jj][xi]);
        }

#pragma unroll
        for (int jj = 0; jj < 16; jj++) {
            float4 o = make_float4(acc[jj][0], acc[jj][1], acc[jj][2], acc[jj][3]);
            *reinterpret_cast<float4*>(op + (size_t)jj * H * W) = o;
        }
    }
}

// Output layout: cv0 (1,192,256,512) | cv1 (1,96,128,256) | cv2 (1,48,64,128)
static constexpr size_t OUT0_ELEMS = (size_t)192 * 256 * 512;  // 25165824
static constexpr size_t OUT1_ELEMS = (size_t)96 * 128 * 256;   //  3145728

__global__ void __launch_bounds__(THREADS, 1)
cost_volume_fused_kernel(const float* __restrict__ L0, const float* __restrict__ R0,
                         const float* __restrict__ L1, const float* __restrict__ R1,
                         const float* __restrict__ L2, const float* __restrict__ R2,
                         float* __restrict__ out)
{
    extern __shared__ float smem[];
    int b = blockIdx.x;
    if (b < 256) {
        cost_volume_row<32, 256, 512, 192>(L0, R0, out, b, smem);
    } else if (b < 256 + 128) {
        cost_volume_row<32, 128, 256, 96>(L1, R1, out + OUT0_ELEMS, b - 256, smem);
    } else {
        cost_volume_row<32, 64, 128, 48>(L2, R2, out + OUT0_ELEMS + OUT1_ELEMS,
                                         b - 256 - 128, smem);
    }
}

extern "C" void kernel_launch(void* const* d_in, const int* in_sizes, int n_in,
                              void* d_out, int out_size)
{
    const float* L0 = (const float*)d_in[0];
    const float* R0 = (const float*)d_in[1];
    const float* L1 = (const float*)d_in[2];
    const float* R1 = (const float*)d_in[3];
    const float* L2 = (const float*)d_in[4];
    const float* R2 = (const float*)d_in[5];
    float* out = (float*)d_out;

    // Worst-case smem: scale 0 -> 32*(512 + 192+512)*4 = 155648 bytes
    constexpr int SMEM_BYTES = 32 * (512 + 192 + 512) * 4;
    static bool attr_set = false;
    if (!attr_set) {
        cudaFuncSetAttribute(cost_volume_fused_kernel,
                             cudaFuncAttributeMaxDynamicSharedMemorySize, SMEM_BYTES);
        attr_set = true;
    }

    // 256 + 128 + 64 = 448 blocks; heavy scale-0 rows first.
    cost_volume_fused_kernel<<<448, THREADS, SMEM_BYTES>>>(L0, R0, L1, R1, L2, R2, out);
}